// round 9
// baseline (speedup 1.0000x reference)
#include <cuda_runtime.h>
#include <math.h>

#define B_   8
#define T_   256
#define MEL_ 128
#define D_   192
#define NC_  20
#define D2_  384
#define NT_  32
#define ND_  4
#define EPS_ 1e-5f

__device__ float g_xp [B_*T_*D_];
__device__ float g_x2 [B_*T_*D_];
__device__ float g_g2 [B_*T_*D_];
__device__ float g_x3 [B_*T_*D_];
__device__ float g_Kd [B_*ND_*D_];
__device__ float g_Vd [B_*ND_*D_];
__device__ float g_Qd [B_*ND_*D_];
__device__ float g_Ed [B_*ND_*D_];
__device__ float g_Fd [B_*ND_*D_];
__device__ float g_Kt [B_*NT_*D_];
__device__ float g_Vt [B_*NT_*D_];
__device__ float g_Qt [B_*NT_*D_];
__device__ float g_Et [B_*NT_*D_];
__device__ float g_Wao [D_*D_];
__device__ float g_bao [D_];
__device__ float g_Wkqd[D_*D_];
__device__ float g_Wkqt[D_*D_];
__device__ float g_pp [B_*16*D_];

__device__ __forceinline__ float cdv(int d) {
    const float L2A = -0.014499569695115089f;   // log2(0.99)
    const float L2E = -0.152003093445049970f;   // log2(0.90)
    float n = (float)(d + 1);
    return (exp2f(n * L2A) - exp2f(n * L2E)) * (0.1f / 0.09f);
}

// ---------------- full-K smem GEMM pieces, 512 threads, 64x64 tile ----------------
// Asf[k*68 + row] (A transposed, padded), Wsf[k*64 + col]
__device__ __forceinline__ void fk_load_A512(float* Asf, const float* __restrict__ A,
                                             int ldA, int m0, int K)
{
    int tid = threadIdx.x;
    int kq = K >> 2;
    for (int idx = tid; idx < 64 * kq; idx += 512) {
        int r = idx / kq, c4 = idx - r * kq;
        float4 v = *(const float4*)&A[(size_t)(m0 + r) * ldA + c4 * 4];
        Asf[(c4 * 4 + 0) * 68 + r] = v.x;
        Asf[(c4 * 4 + 1) * 68 + r] = v.y;
        Asf[(c4 * 4 + 2) * 68 + r] = v.z;
        Asf[(c4 * 4 + 3) * 68 + r] = v.w;
    }
}
__device__ __forceinline__ void fk_load_W512(float* Wsf, const float* __restrict__ W,
                                             int ldW, int n0, int K, bool transB)
{
    int tid = threadIdx.x;
    if (transB) {
        for (int idx = tid; idx < K * 64; idx += 512) {
            int k = idx >> 6, cc = idx & 63;
            Wsf[k * 64 + cc] = W[(size_t)(n0 + cc) * ldW + k];
        }
    } else {
        for (int idx = tid; idx < K * 16; idx += 512) {
            int k = idx >> 4, c4 = idx & 15;
            *(float4*)&Wsf[k * 64 + c4 * 4] =
                *(const float4*)&W[(size_t)k * ldW + n0 + c4 * 4];
        }
    }
}
// each thread: rows ty*2..+1, cols tx*4..+3
template<int K>
__device__ __forceinline__ void fk_compute512(const float* Asf, const float* Wsf, float c[2][4])
{
    int tid = threadIdx.x, tx = tid & 15, ty = tid >> 4;
    const float* pa = Asf + ty * 2;
    const float* pb = Wsf + tx * 4;
    float2 af = *(const float2*)pa;
    float4 bf = *(const float4*)pb;
#pragma unroll 8
    for (int kk = 0; kk < K - 1; kk++) {
        float2 afn = *(const float2*)(pa + (kk + 1) * 68);
        float4 bfn = *(const float4*)(pb + (kk + 1) * 64);
        c[0][0] = fmaf(af.x, bf.x, c[0][0]); c[0][1] = fmaf(af.x, bf.y, c[0][1]);
        c[0][2] = fmaf(af.x, bf.z, c[0][2]); c[0][3] = fmaf(af.x, bf.w, c[0][3]);
        c[1][0] = fmaf(af.y, bf.x, c[1][0]); c[1][1] = fmaf(af.y, bf.y, c[1][1]);
        c[1][2] = fmaf(af.y, bf.z, c[1][2]); c[1][3] = fmaf(af.y, bf.w, c[1][3]);
        af = afn; bf = bfn;
    }
    c[0][0] = fmaf(af.x, bf.x, c[0][0]); c[0][1] = fmaf(af.x, bf.y, c[0][1]);
    c[0][2] = fmaf(af.x, bf.z, c[0][2]); c[0][3] = fmaf(af.x, bf.w, c[0][3]);
    c[1][0] = fmaf(af.y, bf.x, c[1][0]); c[1][1] = fmaf(af.y, bf.y, c[1][1]);
    c[1][2] = fmaf(af.y, bf.z, c[1][2]); c[1][3] = fmaf(af.y, bf.w, c[1][3]);
}

#define ASF_FLOATS (192 * 68)
#define WSF_FLOATS (192 * 64)
#define FK_SMEM  ((ASF_FLOATS + WSF_FLOATS) * 4)

// ---------------- K0: xp GEMM + weight folds ----------------
__global__ void __launch_bounds__(512) k0_comb(
    const float* __restrict__ x, const float* __restrict__ W_in, const float* __restrict__ b_in,
    const float* __restrict__ Wv_a, const float* __restrict__ Wo_a,
    const float* __restrict__ bv_a, const float* __restrict__ bo_a,
    const float* __restrict__ Wk_d, const float* __restrict__ Wq_d,
    const float* __restrict__ Wk_t, const float* __restrict__ Wq_t)
{
    extern __shared__ __align__(16) float sh[];
    float* Asf = sh;
    float* Wsf = sh + ASF_FLOATS;
    int blk = blockIdx.x, tid = threadIdx.x;

    const float* A; const float* W; const float* bias = nullptr; float* C;
    int ldA, ldW, m0, n0, K; bool transB = false;
    if (blk < 96) {
        A = x; ldA = MEL_; W = W_in; ldW = D_; bias = b_in; C = g_xp;
        m0 = (blk / 3) * 64; n0 = (blk % 3) * 64; K = MEL_;
    } else if (blk < 105) {
        int p = blk - 96;
        A = Wv_a; ldA = D_; W = Wo_a; ldW = D_; C = g_Wao;
        m0 = (p / 3) * 64; n0 = (p % 3) * 64; K = D_;
    } else if (blk < 114) {
        int p = blk - 105;
        A = Wk_d; ldA = D_; W = Wq_d; ldW = D_; C = g_Wkqd; transB = true;
        m0 = (p / 3) * 64; n0 = (p % 3) * 64; K = D_;
    } else if (blk < 123) {
        int p = blk - 114;
        A = Wk_t; ldA = D_; W = Wq_t; ldW = D_; C = g_Wkqt; transB = true;
        m0 = (p / 3) * 64; n0 = (p % 3) * 64; K = D_;
    } else {
        if (tid < D_) {
            float s = bo_a[tid];
#pragma unroll 8
            for (int e = 0; e < D_; e++) s = fmaf(bv_a[e], Wo_a[e * D_ + tid], s);
            g_bao[tid] = s;
        }
        return;
    }
    fk_load_A512(Asf, A, ldA, m0, K);
    fk_load_W512(Wsf, W, ldW, n0, K, transB);
    __syncthreads();
    float c[2][4] = {};
    if (K == MEL_) fk_compute512<MEL_>(Asf, Wsf, c);
    else           fk_compute512<D_>(Asf, Wsf, c);
    int tx = tid & 15, ty = tid >> 4;
#pragma unroll
    for (int i = 0; i < 2; i++) {
        int row = m0 + ty * 2 + i, col = n0 + tx * 4;
        float4 o; float* po = &o.x;
#pragma unroll
        for (int j = 0; j < 4; j++) {
            float v = c[i][j];
            if (bias) v += bias[col + j];
            po[j] = v;
        }
        *(float4*)&C[(size_t)row * D_ + col] = o;
    }
}

// ---------------- projKVQ ----------------
__global__ void __launch_bounds__(192) projKVQ(
    float* __restrict__ Ko, float* __restrict__ Vo, float* __restrict__ Qo,
    const float* __restrict__ A, const float* __restrict__ Wk,
    const float* __restrict__ Wv, const float* __restrict__ Wkq, int nUpd, int chunk)
{
    __shared__ float sa[D_];
    int blk = blockIdx.x;
    int b = blk / nUpd, i = blk % nUpd;
    int tid = threadIdx.x;
    sa[tid] = A[(size_t)(b * T_ + i * chunk) * D_ + tid];
    __syncthreads();
    if (tid < 144) {
        int gsel = tid / 48, q = tid % 48;
        const float* W = (gsel == 0) ? Wk : (gsel == 1) ? Wv : Wkq;
        float ax = 0.f, ay = 0.f, az = 0.f, aw = 0.f;
#pragma unroll 16
        for (int kk = 0; kk < D_; kk++) {
            float a = sa[kk];
            float4 w = *(const float4*)&W[kk * D_ + 4 * q];
            ax = fmaf(a, w.x, ax); ay = fmaf(a, w.y, ay);
            az = fmaf(a, w.z, az); aw = fmaf(a, w.w, aw);
        }
        float* O = (gsel == 0) ? Ko : (gsel == 1) ? Vo : Qo;
        float4 o = {ax, ay, az, aw};
        *(float4*)&O[(size_t)blk * D_ + 4 * q] = o;
    }
}

// ---------------- rec_d (+F fold) ----------------
__global__ void __launch_bounds__(256) rec_d_kernel(
    float* __restrict__ ERR, float* __restrict__ F,
    const float* __restrict__ Kmat, const float* __restrict__ Vmat,
    const float* __restrict__ Wao)
{
    __shared__ float sK[ND_][D_ + 1];
    __shared__ float sE[ND_][D_];
    __shared__ float Acf[ND_][ND_];
    int b = blockIdx.x, tid = threadIdx.x;
    for (int idx = tid; idx < ND_ * D_; idx += 256)
        sK[idx / D_][idx % D_] = Kmat[(size_t)b * ND_ * D_ + idx];
    __syncthreads();
    if (tid < 6) {
        const int pi[6] = {1, 2, 2, 3, 3, 3};
        const int pj[6] = {0, 0, 1, 0, 1, 2};
        int i = pi[tid], j = pj[tid];
        float s0 = 0.f, s1 = 0.f;
#pragma unroll 8
        for (int kk = 0; kk < D_; kk += 2) {
            s0 = fmaf(sK[j][kk],     sK[i][kk],     s0);
            s1 = fmaf(sK[j][kk + 1], sK[i][kk + 1], s1);
        }
        Acf[j][i] = cdv(i - 1 - j) * (s0 + s1);
    }
    __syncthreads();
    if (tid < D_) {
        float err[ND_];
#pragma unroll
        for (int i = 0; i < ND_; i++) {
            float s = Vmat[(size_t)(b * ND_ + i) * D_ + tid];
#pragma unroll
            for (int j = 0; j < i; j++) s -= Acf[j][i] * err[j];
            err[i] = s;
            sE[i][tid] = s;
            ERR[(size_t)(b * ND_ + i) * D_ + tid] = s;
        }
    }
    __syncthreads();
    if (tid < 192) {
        int j = tid / 48, q = tid % 48;
        float4 acc = *(float4*)&sE[j][4 * q];
#pragma unroll 8
        for (int e = 0; e < D_; e++) {
            float a = sE[j][e];
            float4 w = *(const float4*)&Wao[e * D_ + 4 * q];
            acc.x = fmaf(a, w.x, acc.x); acc.y = fmaf(a, w.y, acc.y);
            acc.z = fmaf(a, w.z, acc.z); acc.w = fmaf(a, w.w, acc.w);
        }
        *(float4*)&F[(size_t)(b * ND_ + j) * D_ + 4 * q] = acc;
    }
}

// ---------------- x2 fused: x2 = xp + xp@Wao + bao + alpha@F (512 threads) ----------------
__global__ void __launch_bounds__(512) x2_fused(
    const float* __restrict__ xp, const float* __restrict__ Wao, const float* __restrict__ bao,
    const float* __restrict__ Qd, const float* __restrict__ Fd, float* __restrict__ x2)
{
    extern __shared__ __align__(16) float sh[];
    float* Asf = sh;                       // xp tile transposed [192][68]
    float* Wsf = sh + ASF_FLOATS;          // Wao [192][64]
    float* sQ  = Wsf + WSF_FLOATS;         // [4*192]
    float* sF  = sQ + ND_ * D_;            // [4*192]
    float* alph = sF + ND_ * D_;           // [64][4]
    int blk = blockIdx.x;
    int m0 = (blk / 3) * 64, n0 = (blk % 3) * 64;
    int b = m0 >> 8;
    int tid = threadIdx.x, tx = tid & 15, ty = tid >> 4;

    fk_load_A512(Asf, xp, D_, m0, D_);
    fk_load_W512(Wsf, Wao, D_, n0, D_, false);
    for (int idx = tid; idx < ND_ * D_; idx += 512) {
        sQ[idx] = Qd[(size_t)b * ND_ * D_ + idx];
        sF[idx] = Fd[(size_t)b * ND_ * D_ + idx];
    }
    __syncthreads();
    float c[2][4] = {};
    fk_compute512<D_>(Asf, Wsf, c);
    // alpha: 512 threads = 64 rows x 4 j x 2 halves
    {
        int row = tid >> 3, j = (tid >> 1) & 3, half = tid & 1;
        const float* qj = &sQ[j * D_ + half * 96];
        const float* ar = Asf + half * 96 * 68 + row;
        float s0 = 0.f, s1 = 0.f;
#pragma unroll 12
        for (int k = 0; k < 96; k += 2) {
            s0 = fmaf(ar[(k + 0) * 68], qj[k + 0], s0);
            s1 = fmaf(ar[(k + 1) * 68], qj[k + 1], s1);
        }
        float s = s0 + s1;
        s += __shfl_xor_sync(~0u, s, 1);
        if (half == 0) {
            int t = (m0 + row) & (T_ - 1), r = t >> 6;
            alph[row * 4 + j] = (j <= r) ? 0.5f * cdv(r - j) * s : 0.f;
        }
    }
    __syncthreads();
#pragma unroll
    for (int i = 0; i < 2; i++) {
        int lrow = ty * 2 + i, row = m0 + lrow, col = n0 + tx * 4;
        float4 o; float* po = &o.x;
#pragma unroll
        for (int j = 0; j < 4; j++) {
            float v = c[i][j] + bao[col + j] + Asf[(col + j) * 68 + lrow];
#pragma unroll
            for (int jj = 0; jj < ND_; jj++)
                v = fmaf(alph[lrow * 4 + jj], sF[jj * D_ + col + j], v);
            po[j] = v;
        }
        *(float4*)&x2[(size_t)row * D_ + col] = o;
    }
}

// ---------------- glu_ln: LN1 in smem + full-K GLU GEMM (512 threads) ----------------
__global__ void __launch_bounds__(512) glu_ln(
    const float* __restrict__ x2, const float* __restrict__ g1, const float* __restrict__ b1,
    const float* __restrict__ W, const float* __restrict__ bias,
    const float* __restrict__ dw, const float* __restrict__ db,
    const float* __restrict__ bs, const float* __restrict__ bb, float* __restrict__ outp)
{
    extern __shared__ __align__(16) float sh[];
    float* Xs = sh;                        // [192][68]
    float* Wa = Xs + ASF_FLOATS;           // [192][64]
    float* Wg = Wa + WSF_FLOATS;           // [192][64]
    float* pm = Wg + WSF_FLOATS;           // [8][64]
    float* pv = pm + 512;
    float* rowm = pv + 512;
    float* rowr = rowm + 64;
    int blk = blockIdx.x;
    int m0 = (blk / 3) * 64, n0 = (blk % 3) * 64;
    int tid = threadIdx.x, tx = tid & 15, ty = tid >> 4;

    fk_load_A512(Xs, x2, D_, m0, D_);
    for (int idx = tid; idx < D_ * 16; idx += 512) {
        int k = idx >> 4, c4 = idx & 15;
        *(float4*)&Wa[k * 64 + c4 * 4] = *(const float4*)&W[(size_t)k * D2_ + n0 + c4 * 4];
        *(float4*)&Wg[k * 64 + c4 * 4] = *(const float4*)&W[(size_t)k * D2_ + D_ + n0 + c4 * 4];
    }
    __syncthreads();
    {
        int row = tid & 63, part = tid >> 6;   // 8 partials x 24 k each
        float s = 0.f, s2 = 0.f;
#pragma unroll 8
        for (int k = part * 24; k < part * 24 + 24; k++) {
            float v = Xs[k * 68 + row]; s += v; s2 += v * v;
        }
        pm[part * 64 + row] = s; pv[part * 64 + row] = s2;
    }
    __syncthreads();
    if (tid < 64) {
        float ts = 0.f, ts2 = 0.f;
#pragma unroll
        for (int p = 0; p < 8; p++) { ts += pm[p * 64 + tid]; ts2 += pv[p * 64 + tid]; }
        float m = ts / D_;
        rowm[tid] = m;
        rowr[tid] = rsqrtf(ts2 / D_ - m * m + EPS_);
    }
    __syncthreads();
    for (int idx = tid; idx < D_ * 64; idx += 512) {
        int k = idx >> 6, r = idx & 63;
        Xs[k * 68 + r] = (Xs[k * 68 + r] - rowm[r]) * rowr[r] * g1[k] + b1[k];
    }
    __syncthreads();
    float cA[2][4] = {}, cG[2][4] = {};
    {
        const float* pa = Xs + ty * 2;
        const float* pba = Wa + tx * 4;
        const float* pbg = Wg + tx * 4;
        float2 af = *(const float2*)pa;
        float4 ba = *(const float4*)pba;
        float4 bg = *(const float4*)pbg;
#pragma unroll 8
        for (int kk = 0; kk < D_ - 1; kk++) {
            float2 afn = *(const float2*)(pa + (kk + 1) * 68);
            float4 ban = *(const float4*)(pba + (kk + 1) * 64);
            float4 bgn = *(const float4*)(pbg + (kk + 1) * 64);
            cA[0][0] = fmaf(af.x, ba.x, cA[0][0]); cA[0][1] = fmaf(af.x, ba.y, cA[0][1]);
            cA[0][2] = fmaf(af.x, ba.z, cA[0][2]); cA[0][3] = fmaf(af.x, ba.w, cA[0][3]);
            cA[1][0] = fmaf(af.y, ba.x, cA[1][0]); cA[1][1] = fmaf(af.y, ba.y, cA[1][1]);
            cA[1][2] = fmaf(af.y, ba.z, cA[1][2]); cA[1][3] = fmaf(af.y, ba.w, cA[1][3]);
            cG[0][0] = fmaf(af.x, bg.x, cG[0][0]); cG[0][1] = fmaf(af.x, bg.y, cG[0][1]);
            cG[0][2] = fmaf(af.x, bg.z, cG[0][2]); cG[0][3] = fmaf(af.x, bg.w, cG[0][3]);
            cG[1][0] = fmaf(af.y, bg.x, cG[1][0]); cG[1][1] = fmaf(af.y, bg.y, cG[1][1]);
            cG[1][2] = fmaf(af.y, bg.z, cG[1][2]); cG[1][3] = fmaf(af.y, bg.w, cG[1][3]);
            af = afn; ba = ban; bg = bgn;
        }
        cA[0][0] = fmaf(af.x, ba.x, cA[0][0]); cA[0][1] = fmaf(af.x, ba.y, cA[0][1]);
        cA[0][2] = fmaf(af.x, ba.z, cA[0][2]); cA[0][3] = fmaf(af.x, ba.w, cA[0][3]);
        cA[1][0] = fmaf(af.y, ba.x, cA[1][0]); cA[1][1] = fmaf(af.y, ba.y, cA[1][1]);
        cA[1][2] = fmaf(af.y, ba.z, cA[1][2]); cA[1][3] = fmaf(af.y, ba.w, cA[1][3]);
        cG[0][0] = fmaf(af.x, bg.x, cG[0][0]); cG[0][1] = fmaf(af.x, bg.y, cG[0][1]);
        cG[0][2] = fmaf(af.x, bg.z, cG[0][2]); cG[0][3] = fmaf(af.x, bg.w, cG[0][3]);
        cG[1][0] = fmaf(af.y, bg.x, cG[1][0]); cG[1][1] = fmaf(af.y, bg.y, cG[1][1]);
        cG[1][2] = fmaf(af.y, bg.z, cG[1][2]); cG[1][3] = fmaf(af.y, bg.w, cG[1][3]);
    }
#pragma unroll
    for (int i = 0; i < 2; i++) {
        int row = m0 + ty * 2 + i, col = n0 + tx * 4;
        float4 o; float* po = &o.x;
#pragma unroll
        for (int j = 0; j < 4; j++) {
            float a = cA[i][j] + bias[col + j];
            float g = cG[i][j] + bias[D_ + col + j];
            float h = a * (1.f / (1.f + expf(-g)));
            h = h * dw[col + j] + db[col + j];
            h = h * bs[col + j] + bb[col + j];
            h = h * (1.f / (1.f + expf(-h)));
            po[j] = h;
        }
        *(float4*)&outp[(size_t)row * D_ + col] = o;
    }
}

// ---------------- pw2 GEMM (512 threads, residual) ----------------
__global__ void __launch_bounds__(512) gemm_pw2(
    const float* __restrict__ A, const float* __restrict__ W,
    const float* __restrict__ bias, const float* __restrict__ res, float* __restrict__ C)
{
    extern __shared__ __align__(16) float sh[];
    float* Asf = sh;
    float* Wsf = sh + ASF_FLOATS;
    int blk = blockIdx.x;
    int m0 = (blk / 3) * 64, n0 = (blk % 3) * 64;
    int tid = threadIdx.x, tx = tid & 15, ty = tid >> 4;
    fk_load_A512(Asf, A, D_, m0, D_);
    fk_load_W512(Wsf, W, D_, n0, D_, false);
    __syncthreads();
    float c[2][4] = {};
    fk_compute512<D_>(Asf, Wsf, c);
#pragma unroll
    for (int i = 0; i < 2; i++) {
        int row = m0 + ty * 2 + i, col = n0 + tx * 4;
        float4 rv = *(const float4*)&res[(size_t)row * D_ + col];
        float4 o;
        o.x = c[i][0] + bias[col + 0] + rv.x;
        o.y = c[i][1] + bias[col + 1] + rv.y;
        o.z = c[i][2] + bias[col + 2] + rv.z;
        o.w = c[i][3] + bias[col + 3] + rv.w;
        *(float4*)&C[(size_t)row * D_ + col] = o;
    }
}

// ---------------- rec_t ----------------
__global__ void __launch_bounds__(256) rec_t_kernel(
    float* __restrict__ ERR, const float* __restrict__ Kmat, const float* __restrict__ Vmat)
{
    __shared__ float sK[NT_][D_ + 1];
    __shared__ float Acf[NT_][NT_];
    __shared__ float cd[NT_];
    int b = blockIdx.x, tid = threadIdx.x;
    if (tid < NT_) cd[tid] = cdv(tid);
    for (int idx = tid; idx < NT_ * D_; idx += 256)
        sK[idx / D_][idx % D_] = Kmat[(size_t)b * NT_ * D_ + idx];
    __syncthreads();
    const int NP = NT_ * (NT_ - 1) / 2;
    for (int p = tid; p < NP; p += 256) {
        int i = (int)((1.0f + sqrtf(1.0f + 8.0f * (float)p)) * 0.5f);
        while (i * (i - 1) / 2 > p) i--;
        while ((i + 1) * i / 2 <= p) i++;
        int j = p - i * (i - 1) / 2;
        float s0 = 0.f, s1 = 0.f;
#pragma unroll 8
        for (int kk = 0; kk < D_; kk += 2) {
            s0 = fmaf(sK[j][kk],     sK[i][kk],     s0);
            s1 = fmaf(sK[j][kk + 1], sK[i][kk + 1], s1);
        }
        Acf[j][i] = cd[i - 1 - j] * (s0 + s1);
    }
    __syncthreads();
    if (tid < D_) {
        float err[NT_];
#pragma unroll
        for (int i = 0; i < NT_; i++) {
            float a0 = 0.f, a1 = 0.f;
#pragma unroll
            for (int j = 0; j < i; j++) {
                if (j & 1) a1 = fmaf(Acf[j][i], err[j], a1);
                else       a0 = fmaf(Acf[j][i], err[j], a0);
            }
            err[i] = Vmat[(size_t)(b * NT_ + i) * D_ + tid] - a0 - a1;
            ERR[(size_t)(b * NT_ + i) * D_ + tid] = err[i];
        }
    }
}

// ---------------- qkfinal ----------------
__global__ void __launch_bounds__(192) qkfinal(
    const float* __restrict__ x3, const float* __restrict__ Kt, const float* __restrict__ Et,
    const float* __restrict__ g2, const float* __restrict__ b2, float* __restrict__ pp)
{
    extern __shared__ __align__(16) float sh[];
    float (*sKT)[33] = (float (*)[33])sh;
    float* sEt = sh + 192 * 33;
    float* red = sEt + NT_ * D_;
    float* alpha = red + 192;
    float* cd = alpha + 32;
    float* lred = cd + 32;
    int blk = blockIdx.x;
    int b = blk >> 4, tc = blk & 15, t0 = tc * 16;
    int tid = threadIdx.x;
    if (tid < NT_) cd[tid] = cdv(tid);
    for (int idx = tid; idx < NT_ * D_; idx += 192) {
        int j = idx / D_, e = idx % D_;
        sKT[e][j] = Kt[(size_t)(b * NT_ + j) * D_ + e];
        sEt[idx] = Et[(size_t)b * NT_ * D_ + idx];
    }
    __syncthreads();
    int j = tid & 31, g = tid >> 5;
    float ps = 0.f;
    for (int tt = 0; tt < 16; tt++) {
        int t = t0 + tt, row = b * T_ + t, r = t >> 3;
        {
            const float* qr = x3 + (size_t)row * D_;
            float part = 0.f;
#pragma unroll
            for (int u = 0; u < 32; u++) part = fmaf(qr[g * 32 + u], sKT[g * 32 + u][j], part);
            red[j * 6 + g] = part;
        }
        __syncthreads();
        if (tid < NT_) {
            float s = 0.f;
#pragma unroll
            for (int gg = 0; gg < 6; gg++) s += red[tid * 6 + gg];
            alpha[tid] = (tid <= r) ? cd[r - tid] * s : 0.f;
        }
        __syncthreads();
        float s = 0.f;
        for (int jj = 0; jj <= r; jj++) s = fmaf(alpha[jj], sEt[jj * D_ + tid], s);
        float x4 = x3[(size_t)row * D_ + tid] + 0.5f * s;
        float sm = x4, s2 = x4 * x4;
#pragma unroll
        for (int o = 16; o > 0; o >>= 1) {
            sm += __shfl_xor_sync(~0u, sm, o);
            s2 += __shfl_xor_sync(~0u, s2, o);
        }
        if ((tid & 31) == 0) { lred[tid >> 5] = sm; lred[6 + (tid >> 5)] = s2; }
        __syncthreads();
        float ts = 0.f, ts2 = 0.f;
#pragma unroll
        for (int i = 0; i < 6; i++) { ts += lred[i]; ts2 += lred[6 + i]; }
        float m = ts / D_;
        float var = ts2 / D_ - m * m;
        ps += (x4 - m) * rsqrtf(var + EPS_) * g2[tid] + b2[tid];
        __syncthreads();
    }
    pp[(size_t)(b * 16 + tc) * D_ + tid] = ps;
}

// ---------------- pool + classifier ----------------
__global__ void __launch_bounds__(192) poolcls(
    const float* __restrict__ pp, const float* __restrict__ Wc,
    const float* __restrict__ bc, float* __restrict__ out)
{
    __shared__ float pooled[D_];
    int b = blockIdx.x, tid = threadIdx.x;
    float s = 0.f;
#pragma unroll
    for (int q = 0; q < 16; q++) s += pp[(size_t)(b * 16 + q) * D_ + tid];
    pooled[tid] = s * (1.f / T_);
    __syncthreads();
    if (tid < NC_) {
        float acc = bc[tid];
#pragma unroll 8
        for (int e = 0; e < D_; e++) acc = fmaf(pooled[e], Wc[e * NC_ + tid], acc);
        out[b * NC_ + tid] = acc;
    }
}

// =====================================================================
extern "C" void kernel_launch(void* const* d_in, const int* in_sizes, int n_in,
                              void* d_out, int out_size)
{
    const float* x     = (const float*)d_in[0];
    const float* W_in  = (const float*)d_in[1];
    const float* b_in  = (const float*)d_in[2];
    const float* Wv_a  = (const float*)d_in[3];
    const float* bv_a  = (const float*)d_in[4];
    const float* Wo_a  = (const float*)d_in[5];
    const float* bo_a  = (const float*)d_in[6];
    const float* ln1_g = (const float*)d_in[7];
    const float* ln1_b = (const float*)d_in[8];
    const float* pw1_w = (const float*)d_in[9];
    const float* pw1_b = (const float*)d_in[10];
    const float* dw_w  = (const float*)d_in[11];
    const float* dw_b  = (const float*)d_in[12];
    const float* bn_s  = (const float*)d_in[13];
    const float* bn_b  = (const float*)d_in[14];
    const float* pw2_w = (const float*)d_in[15];
    const float* pw2_b = (const float*)d_in[16];
    const float* Wk_t  = (const float*)d_in[17];
    const float* Wv_t  = (const float*)d_in[18];
    const float* Wq_t  = (const float*)d_in[19];
    const float* Wk_d  = (const float*)d_in[20];
    const float* Wv_d  = (const float*)d_in[21];
    const float* Wq_d  = (const float*)d_in[22];
    const float* ln2_g = (const float*)d_in[23];
    const float* ln2_b = (const float*)d_in[24];
    const float* Wc    = (const float*)d_in[25];
    const float* bc    = (const float*)d_in[26];
    float* out = (float*)d_out;

    float *xp, *x2, *g2p, *x3, *Kd, *Vd, *Qd, *Ed, *Fd, *Kt, *Vt, *Qt, *Et;
    float *Wao, *bao, *Wkqd, *Wkqt, *pp;
    cudaGetSymbolAddress((void**)&xp,   g_xp);
    cudaGetSymbolAddress((void**)&x2,   g_x2);
    cudaGetSymbolAddress((void**)&g2p,  g_g2);
    cudaGetSymbolAddress((void**)&x3,   g_x3);
    cudaGetSymbolAddress((void**)&Kd,   g_Kd);
    cudaGetSymbolAddress((void**)&Vd,   g_Vd);
    cudaGetSymbolAddress((void**)&Qd,   g_Qd);
    cudaGetSymbolAddress((void**)&Ed,   g_Ed);
    cudaGetSymbolAddress((void**)&Fd,   g_Fd);
    cudaGetSymbolAddress((void**)&Kt,   g_Kt);
    cudaGetSymbolAddress((void**)&Vt,   g_Vt);
    cudaGetSymbolAddress((void**)&Qt,   g_Qt);
    cudaGetSymbolAddress((void**)&Et,   g_Et);
    cudaGetSymbolAddress((void**)&Wao,  g_Wao);
    cudaGetSymbolAddress((void**)&bao,  g_bao);
    cudaGetSymbolAddress((void**)&Wkqd, g_Wkqd);
    cudaGetSymbolAddress((void**)&Wkqt, g_Wkqt);
    cudaGetSymbolAddress((void**)&pp,   g_pp);

    const int X2_SMEM  = FK_SMEM + (ND_ * D_ * 2 + 256) * 4;
    const int GLU_SMEM = (ASF_FLOATS + 2 * WSF_FLOATS + 512 + 512 + 64 + 64) * 4;
    const int QKF_SMEM = (192 * 33 + NT_ * D_ + 192 + 32 + 32 + 12) * 4;
    cudaFuncSetAttribute(k0_comb,  cudaFuncAttributeMaxDynamicSharedMemorySize, FK_SMEM);
    cudaFuncSetAttribute(x2_fused, cudaFuncAttributeMaxDynamicSharedMemorySize, X2_SMEM);
    cudaFuncSetAttribute(glu_ln,   cudaFuncAttributeMaxDynamicSharedMemorySize, GLU_SMEM);
    cudaFuncSetAttribute(gemm_pw2, cudaFuncAttributeMaxDynamicSharedMemorySize, FK_SMEM);
    cudaFuncSetAttribute(qkfinal,  cudaFuncAttributeMaxDynamicSharedMemorySize, QKF_SMEM);

    k0_comb<<<124, 512, FK_SMEM>>>(x, W_in, b_in, Wv_a, Wo_a, bv_a, bo_a,
                                   Wk_d, Wq_d, Wk_t, Wq_t);
    projKVQ<<<B_ * ND_, 192>>>(Kd, Vd, Qd, xp, Wk_d, Wv_d, Wkqd, ND_, 64);
    rec_d_kernel<<<B_, 256>>>(Ed, Fd, Kd, Vd, Wao);
    x2_fused<<<96, 512, X2_SMEM>>>(xp, Wao, bao, Qd, Fd, x2);
    glu_ln<<<96, 512, GLU_SMEM>>>(x2, ln1_g, ln1_b, pw1_w, pw1_b, dw_w, dw_b, bn_s, bn_b, g2p);
    gemm_pw2<<<96, 512, FK_SMEM>>>(g2p, pw2_w, pw2_b, x2, x3);
    projKVQ<<<B_ * NT_, 192>>>(Kt, Vt, Qt, x3, Wk_t, Wv_t, Wkqt, NT_, 8);
    rec_t_kernel<<<B_, 256>>>(Et, Kt, Vt);
    qkfinal<<<B_ * 16, 192, QKF_SMEM>>>(x3, Qt, Et, ln2_g, ln2_b, pp);
    poolcls<<<B_, 192>>>(pp, Wc, bc, out);
}

// round 10
// speedup vs baseline: 1.0226x; 1.0226x over previous
#include <cuda_runtime.h>
#include <math.h>

#define B_   8
#define T_   256
#define MEL_ 128
#define D_   192
#define NC_  20
#define D2_  384
#define NT_  32
#define ND_  4
#define EPS_ 1e-5f

__device__ float g_xp [B_*T_*D_];
__device__ float g_x2 [B_*T_*D_];
__device__ float g_g2 [B_*T_*D_];
__device__ float g_x3 [B_*T_*D_];
__device__ float g_Kd [B_*ND_*D_];
__device__ float g_Vd [B_*ND_*D_];
__device__ float g_Qd [B_*ND_*D_];
__device__ float g_Ed [B_*ND_*D_];
__device__ float g_Fd [B_*ND_*D_];
__device__ float g_Kt [B_*NT_*D_];
__device__ float g_Vt [B_*NT_*D_];
__device__ float g_Qt [B_*NT_*D_];
__device__ float g_Et [B_*NT_*D_];
__device__ float g_Wao [D_*D_];
__device__ float g_bao [D_];
__device__ float g_Wkqd[D_*D_];
__device__ float g_Wkqt[D_*D_];
__device__ float g_pp [B_*16*D_];

__device__ __forceinline__ float cdv(int d) {
    const float L2A = -0.014499569695115089f;   // log2(0.99)
    const float L2E = -0.152003093445049970f;   // log2(0.90)
    float n = (float)(d + 1);
    return (exp2f(n * L2A) - exp2f(n * L2E)) * (0.1f / 0.09f);
}

// ================= full-K smem GEMM pieces: 256 threads, 64x32 tile =================
// Asf[k*68 + row]  (A transposed, 64 rows, padded stride 68)
// Wsf[k*32 + col]  (32 cols)
// thread map: tx = tid&15 (2 cols each), ty = tid>>4 (4 rows each); c[4][2]
#define AST 68
__device__ __forceinline__ void fkA(float* Asf, const float* __restrict__ A,
                                    int ldA, int m0, int K)
{
    int tid = threadIdx.x;
    int kq = K >> 2;
    for (int idx = tid; idx < 64 * kq; idx += 256) {
        int r = idx / kq, c4 = idx - r * kq;
        float4 v = *(const float4*)&A[(size_t)(m0 + r) * ldA + c4 * 4];
        Asf[(c4 * 4 + 0) * AST + r] = v.x;
        Asf[(c4 * 4 + 1) * AST + r] = v.y;
        Asf[(c4 * 4 + 2) * AST + r] = v.z;
        Asf[(c4 * 4 + 3) * AST + r] = v.w;
    }
}
__device__ __forceinline__ void fkW(float* Wsf, const float* __restrict__ W,
                                    int ldW, int n0, int K, bool transB)
{
    int tid = threadIdx.x;
    if (transB) {
        for (int idx = tid; idx < K * 32; idx += 256) {
            int k = idx >> 5, cc = idx & 31;
            Wsf[k * 32 + cc] = W[(size_t)(n0 + cc) * ldW + k];
        }
    } else {
        for (int idx = tid; idx < K * 8; idx += 256) {
            int k = idx >> 3, c4 = idx & 7;
            *(float4*)&Wsf[k * 32 + c4 * 4] =
                *(const float4*)&W[(size_t)k * ldW + n0 + c4 * 4];
        }
    }
}
template<int K>
__device__ __forceinline__ void fkC(const float* Asf, const float* Wsf, float c[4][2])
{
    int tid = threadIdx.x, tx = tid & 15, ty = tid >> 4;
    const float* pa = Asf + ty * 4;
    const float* pb = Wsf + tx * 2;
    float4 af = *(const float4*)pa;
    float2 bf = *(const float2*)pb;
#pragma unroll 8
    for (int kk = 0; kk < K - 1; kk++) {
        float4 afn = *(const float4*)(pa + (kk + 1) * AST);
        float2 bfn = *(const float2*)(pb + (kk + 1) * 32);
        c[0][0] = fmaf(af.x, bf.x, c[0][0]); c[0][1] = fmaf(af.x, bf.y, c[0][1]);
        c[1][0] = fmaf(af.y, bf.x, c[1][0]); c[1][1] = fmaf(af.y, bf.y, c[1][1]);
        c[2][0] = fmaf(af.z, bf.x, c[2][0]); c[2][1] = fmaf(af.z, bf.y, c[2][1]);
        c[3][0] = fmaf(af.w, bf.x, c[3][0]); c[3][1] = fmaf(af.w, bf.y, c[3][1]);
        af = afn; bf = bfn;
    }
    c[0][0] = fmaf(af.x, bf.x, c[0][0]); c[0][1] = fmaf(af.x, bf.y, c[0][1]);
    c[1][0] = fmaf(af.y, bf.x, c[1][0]); c[1][1] = fmaf(af.y, bf.y, c[1][1]);
    c[2][0] = fmaf(af.z, bf.x, c[2][0]); c[2][1] = fmaf(af.z, bf.y, c[2][1]);
    c[3][0] = fmaf(af.w, bf.x, c[3][0]); c[3][1] = fmaf(af.w, bf.y, c[3][1]);
}

#define ASF_FLOATS (192 * AST)
#define WSF_FLOATS (192 * 32)
#define GEMM_SMEM  ((ASF_FLOATS + WSF_FLOATS) * 4)

// ---------------- K0: xp GEMM (192 tiles) + weight folds (54 tiles) + bao ----------------
__global__ void __launch_bounds__(256) k0_comb(
    const float* __restrict__ x, const float* __restrict__ W_in, const float* __restrict__ b_in,
    const float* __restrict__ Wv_a, const float* __restrict__ Wo_a,
    const float* __restrict__ bv_a, const float* __restrict__ bo_a,
    const float* __restrict__ Wk_d, const float* __restrict__ Wq_d,
    const float* __restrict__ Wk_t, const float* __restrict__ Wq_t)
{
    extern __shared__ __align__(16) float sh[];
    float* Asf = sh;
    float* Wsf = sh + ASF_FLOATS;
    int blk = blockIdx.x, tid = threadIdx.x;

    const float* A; const float* W; const float* bias = nullptr; float* C;
    int ldA, ldW, m0, n0, K; bool transB = false;
    if (blk < 192) {
        A = x; ldA = MEL_; W = W_in; ldW = D_; bias = b_in; C = g_xp;
        m0 = (blk / 3) * 32 * 2; n0 = (blk % 3) * 64;   // careful: recompute below
        m0 = (blk / 6) * 64; n0 = (blk % 6) * 32;
        K = MEL_;
    } else if (blk < 246) {
        int p = blk - 192;
        int z = p / 18, q = p % 18;
        m0 = (q / 6) * 64; n0 = (q % 6) * 32; K = D_;
        if (z == 0)      { A = Wv_a; W = Wo_a; C = g_Wao; }
        else if (z == 1) { A = Wk_d; W = Wq_d; C = g_Wkqd; transB = true; }
        else             { A = Wk_t; W = Wq_t; C = g_Wkqt; transB = true; }
        ldA = D_; ldW = D_;
    } else {
        if (tid < D_) {
            float s = bo_a[tid];
#pragma unroll 8
            for (int e = 0; e < D_; e++) s = fmaf(bv_a[e], Wo_a[e * D_ + tid], s);
            g_bao[tid] = s;
        }
        return;
    }
    fkA(Asf, A, ldA, m0, K);
    fkW(Wsf, W, ldW, n0, K, transB);
    __syncthreads();
    float c[4][2] = {};
    if (K == MEL_) fkC<MEL_>(Asf, Wsf, c);
    else           fkC<D_>(Asf, Wsf, c);
    int tx = tid & 15, ty = tid >> 4;
#pragma unroll
    for (int i = 0; i < 4; i++) {
        int row = m0 + ty * 4 + i, col = n0 + tx * 2;
        float2 o;
        o.x = c[i][0]; o.y = c[i][1];
        if (bias) { o.x += bias[col]; o.y += bias[col + 1]; }
        *(float2*)&C[(size_t)row * D_ + col] = o;
    }
}

// ---------------- projKVQ ----------------
__global__ void __launch_bounds__(192) projKVQ(
    float* __restrict__ Ko, float* __restrict__ Vo, float* __restrict__ Qo,
    const float* __restrict__ A, const float* __restrict__ Wk,
    const float* __restrict__ Wv, const float* __restrict__ Wkq, int nUpd, int chunk)
{
    __shared__ float sa[D_];
    int blk = blockIdx.x;
    int b = blk / nUpd, i = blk % nUpd;
    int tid = threadIdx.x;
    sa[tid] = A[(size_t)(b * T_ + i * chunk) * D_ + tid];
    __syncthreads();
    if (tid < 144) {
        int gsel = tid / 48, q = tid % 48;
        const float* W = (gsel == 0) ? Wk : (gsel == 1) ? Wv : Wkq;
        float ax = 0.f, ay = 0.f, az = 0.f, aw = 0.f;
#pragma unroll 16
        for (int kk = 0; kk < D_; kk++) {
            float a = sa[kk];
            float4 w = *(const float4*)&W[kk * D_ + 4 * q];
            ax = fmaf(a, w.x, ax); ay = fmaf(a, w.y, ay);
            az = fmaf(a, w.z, az); aw = fmaf(a, w.w, aw);
        }
        float* O = (gsel == 0) ? Ko : (gsel == 1) ? Vo : Qo;
        float4 o = {ax, ay, az, aw};
        *(float4*)&O[(size_t)blk * D_ + 4 * q] = o;
    }
}

// ---------------- rec_d (+F fold) ----------------
__global__ void __launch_bounds__(256) rec_d_kernel(
    float* __restrict__ ERR, float* __restrict__ F,
    const float* __restrict__ Kmat, const float* __restrict__ Vmat,
    const float* __restrict__ Wao)
{
    __shared__ float sK[ND_][D_ + 1];
    __shared__ float sE[ND_][D_];
    __shared__ float Acf[ND_][ND_];
    int b = blockIdx.x, tid = threadIdx.x;
    for (int idx = tid; idx < ND_ * D_; idx += 256)
        sK[idx / D_][idx % D_] = Kmat[(size_t)b * ND_ * D_ + idx];
    __syncthreads();
    if (tid < 6) {
        const int pi[6] = {1, 2, 2, 3, 3, 3};
        const int pj[6] = {0, 0, 1, 0, 1, 2};
        int i = pi[tid], j = pj[tid];
        float s0 = 0.f, s1 = 0.f;
#pragma unroll 8
        for (int kk = 0; kk < D_; kk += 2) {
            s0 = fmaf(sK[j][kk],     sK[i][kk],     s0);
            s1 = fmaf(sK[j][kk + 1], sK[i][kk + 1], s1);
        }
        Acf[j][i] = cdv(i - 1 - j) * (s0 + s1);
    }
    __syncthreads();
    if (tid < D_) {
        float err[ND_];
#pragma unroll
        for (int i = 0; i < ND_; i++) {
            float s = Vmat[(size_t)(b * ND_ + i) * D_ + tid];
#pragma unroll
            for (int j = 0; j < i; j++) s -= Acf[j][i] * err[j];
            err[i] = s;
            sE[i][tid] = s;
            ERR[(size_t)(b * ND_ + i) * D_ + tid] = s;
        }
    }
    __syncthreads();
    if (tid < 192) {
        int j = tid / 48, q = tid % 48;
        float4 acc = *(float4*)&sE[j][4 * q];
#pragma unroll 8
        for (int e = 0; e < D_; e++) {
            float a = sE[j][e];
            float4 w = *(const float4*)&Wao[e * D_ + 4 * q];
            acc.x = fmaf(a, w.x, acc.x); acc.y = fmaf(a, w.y, acc.y);
            acc.z = fmaf(a, w.z, acc.z); acc.w = fmaf(a, w.w, acc.w);
        }
        *(float4*)&F[(size_t)(b * ND_ + j) * D_ + 4 * q] = acc;
    }
}

// ---------------- x2 fused: x2 = xp + xp@Wao + bao + alpha@F (64x32 tiles, grid 192) ----------------
__global__ void __launch_bounds__(256) x2_fused(
    const float* __restrict__ xp, const float* __restrict__ Wao, const float* __restrict__ bao,
    const float* __restrict__ Qd, const float* __restrict__ Fd, float* __restrict__ x2)
{
    extern __shared__ __align__(16) float sh[];
    float* Asf = sh;                       // xp tile transposed [192][68]
    float* Wsf = sh + ASF_FLOATS;          // Wao [192][32]
    float* sQ  = Wsf + WSF_FLOATS;         // [4*192]
    float* sF  = sQ + ND_ * D_;            // [4*192]
    float* alph = sF + ND_ * D_;           // [64][4]
    int blk = blockIdx.x;
    int m0 = (blk / 6) * 64, n0 = (blk % 6) * 32;
    int b = m0 >> 8;
    int tid = threadIdx.x, tx = tid & 15, ty = tid >> 4;

    fkA(Asf, xp, D_, m0, D_);
    fkW(Wsf, Wao, D_, n0, D_, false);
    for (int idx = tid; idx < ND_ * D_; idx += 256) {
        sQ[idx] = Qd[(size_t)b * ND_ * D_ + idx];
        sF[idx] = Fd[(size_t)b * ND_ * D_ + idx];
    }
    __syncthreads();
    float c[4][2] = {};
    fkC<D_>(Asf, Wsf, c);
    // alpha: 256 threads = 64 rows x 4 j
    {
        int row = tid >> 2, j = tid & 3;
        const float* qj = &sQ[j * D_];
        float s0 = 0.f, s1 = 0.f, s2 = 0.f, s3 = 0.f;
#pragma unroll 12
        for (int k = 0; k < D_; k += 4) {
            s0 = fmaf(Asf[(k + 0) * AST + row], qj[k + 0], s0);
            s1 = fmaf(Asf[(k + 1) * AST + row], qj[k + 1], s1);
            s2 = fmaf(Asf[(k + 2) * AST + row], qj[k + 2], s2);
            s3 = fmaf(Asf[(k + 3) * AST + row], qj[k + 3], s3);
        }
        float s = (s0 + s1) + (s2 + s3);
        int t = (m0 + row) & (T_ - 1), r = t >> 6;
        alph[row * 4 + j] = (j <= r) ? 0.5f * cdv(r - j) * s : 0.f;
    }
    __syncthreads();
#pragma unroll
    for (int i = 0; i < 4; i++) {
        int lrow = ty * 4 + i, row = m0 + lrow, col = n0 + tx * 2;
        float2 o;
        float v0 = c[i][0] + bao[col + 0] + Asf[(col + 0) * AST + lrow];
        float v1 = c[i][1] + bao[col + 1] + Asf[(col + 1) * AST + lrow];
#pragma unroll
        for (int jj = 0; jj < ND_; jj++) {
            float al = alph[lrow * 4 + jj];
            v0 = fmaf(al, sF[jj * D_ + col + 0], v0);
            v1 = fmaf(al, sF[jj * D_ + col + 1], v1);
        }
        o.x = v0; o.y = v1;
        *(float2*)&x2[(size_t)row * D_ + col] = o;
    }
}

// ---------------- glu_ln: LN1 in smem + GLU GEMM (64x32 tiles, grid 192) ----------------
__global__ void __launch_bounds__(256) glu_ln(
    const float* __restrict__ x2, const float* __restrict__ g1, const float* __restrict__ b1,
    const float* __restrict__ W, const float* __restrict__ bias,
    const float* __restrict__ dw, const float* __restrict__ db,
    const float* __restrict__ bs, const float* __restrict__ bb, float* __restrict__ outp)
{
    extern __shared__ __align__(16) float sh[];
    float* Xs = sh;                        // [192][68]
    float* Wa = Xs + ASF_FLOATS;           // [192][32]
    float* Wg = Wa + WSF_FLOATS;           // [192][32]
    float* pm = Wg + WSF_FLOATS;           // [4][64]
    float* pv = pm + 256;
    float* rowm = pv + 256;
    float* rowr = rowm + 64;
    int blk = blockIdx.x;
    int m0 = (blk / 6) * 64, n0 = (blk % 6) * 32;
    int tid = threadIdx.x, tx = tid & 15, ty = tid >> 4;

    fkA(Xs, x2, D_, m0, D_);
    for (int idx = tid; idx < D_ * 8; idx += 256) {
        int k = idx >> 3, c4 = idx & 7;
        *(float4*)&Wa[k * 32 + c4 * 4] = *(const float4*)&W[(size_t)k * D2_ + n0 + c4 * 4];
        *(float4*)&Wg[k * 32 + c4 * 4] = *(const float4*)&W[(size_t)k * D2_ + D_ + n0 + c4 * 4];
    }
    __syncthreads();
    {
        int row = tid & 63, part = tid >> 6;
        float s = 0.f, s2 = 0.f;
#pragma unroll 8
        for (int k = part * 48; k < part * 48 + 48; k++) {
            float v = Xs[k * AST + row]; s += v; s2 += v * v;
        }
        pm[part * 64 + row] = s; pv[part * 64 + row] = s2;
    }
    __syncthreads();
    if (tid < 64) {
        float ts  = pm[tid] + pm[64 + tid] + pm[128 + tid] + pm[192 + tid];
        float ts2 = pv[tid] + pv[64 + tid] + pv[128 + tid] + pv[192 + tid];
        float m = ts / D_;
        rowm[tid] = m;
        rowr[tid] = rsqrtf(ts2 / D_ - m * m + EPS_);
    }
    __syncthreads();
    for (int idx = tid; idx < D_ * 64; idx += 256) {
        int k = idx >> 6, r = idx & 63;
        Xs[k * AST + r] = (Xs[k * AST + r] - rowm[r]) * rowr[r] * g1[k] + b1[k];
    }
    __syncthreads();
    float cA[4][2] = {}, cG[4][2] = {};
    {
        const float* pa = Xs + ty * 4;
        const float* pba = Wa + tx * 2;
        const float* pbg = Wg + tx * 2;
        float4 af = *(const float4*)pa;
        float2 ba = *(const float2*)pba;
        float2 bg = *(const float2*)pbg;
#pragma unroll 8
        for (int kk = 0; kk < D_ - 1; kk++) {
            float4 afn = *(const float4*)(pa + (kk + 1) * AST);
            float2 ban = *(const float2*)(pba + (kk + 1) * 32);
            float2 bgn = *(const float2*)(pbg + (kk + 1) * 32);
            cA[0][0] = fmaf(af.x, ba.x, cA[0][0]); cA[0][1] = fmaf(af.x, ba.y, cA[0][1]);
            cA[1][0] = fmaf(af.y, ba.x, cA[1][0]); cA[1][1] = fmaf(af.y, ba.y, cA[1][1]);
            cA[2][0] = fmaf(af.z, ba.x, cA[2][0]); cA[2][1] = fmaf(af.z, ba.y, cA[2][1]);
            cA[3][0] = fmaf(af.w, ba.x, cA[3][0]); cA[3][1] = fmaf(af.w, ba.y, cA[3][1]);
            cG[0][0] = fmaf(af.x, bg.x, cG[0][0]); cG[0][1] = fmaf(af.x, bg.y, cG[0][1]);
            cG[1][0] = fmaf(af.y, bg.x, cG[1][0]); cG[1][1] = fmaf(af.y, bg.y, cG[1][1]);
            cG[2][0] = fmaf(af.z, bg.x, cG[2][0]); cG[2][1] = fmaf(af.z, bg.y, cG[2][1]);
            cG[3][0] = fmaf(af.w, bg.x, cG[3][0]); cG[3][1] = fmaf(af.w, bg.y, cG[3][1]);
            af = afn; ba = ban; bg = bgn;
        }
        cA[0][0] = fmaf(af.x, ba.x, cA[0][0]); cA[0][1] = fmaf(af.x, ba.y, cA[0][1]);
        cA[1][0] = fmaf(af.y, ba.x, cA[1][0]); cA[1][1] = fmaf(af.y, ba.y, cA[1][1]);
        cA[2][0] = fmaf(af.z, ba.x, cA[2][0]); cA[2][1] = fmaf(af.z, ba.y, cA[2][1]);
        cA[3][0] = fmaf(af.w, ba.x, cA[3][0]); cA[3][1] = fmaf(af.w, ba.y, cA[3][1]);
        cG[0][0] = fmaf(af.x, bg.x, cG[0][0]); cG[0][1] = fmaf(af.x, bg.y, cG[0][1]);
        cG[1][0] = fmaf(af.y, bg.x, cG[1][0]); cG[1][1] = fmaf(af.y, bg.y, cG[1][1]);
        cG[2][0] = fmaf(af.z, bg.x, cG[2][0]); cG[2][1] = fmaf(af.z, bg.y, cG[2][1]);
        cG[3][0] = fmaf(af.w, bg.x, cG[3][0]); cG[3][1] = fmaf(af.w, bg.y, cG[3][1]);
    }
#pragma unroll
    for (int i = 0; i < 4; i++) {
        int row = m0 + ty * 4 + i, col = n0 + tx * 2;
        float2 o;
#pragma unroll
        for (int j = 0; j < 2; j++) {
            float a = cA[i][j] + bias[col + j];
            float g = cG[i][j] + bias[D_ + col + j];
            float h = a * (1.f / (1.f + expf(-g)));
            h = h * dw[col + j] + db[col + j];
            h = h * bs[col + j] + bb[col + j];
            h = h * (1.f / (1.f + expf(-h)));
            (j == 0 ? o.x : o.y) = h;
        }
        *(float2*)&outp[(size_t)row * D_ + col] = o;
    }
}

// ---------------- pw2 GEMM (64x32 tiles, grid 192, residual) ----------------
__global__ void __launch_bounds__(256) gemm_pw2(
    const float* __restrict__ A, const float* __restrict__ W,
    const float* __restrict__ bias, const float* __restrict__ res, float* __restrict__ C)
{
    extern __shared__ __align__(16) float sh[];
    float* Asf = sh;
    float* Wsf = sh + ASF_FLOATS;
    int blk = blockIdx.x;
    int m0 = (blk / 6) * 64, n0 = (blk % 6) * 32;
    int tid = threadIdx.x, tx = tid & 15, ty = tid >> 4;
    fkA(Asf, A, D_, m0, D_);
    fkW(Wsf, W, D_, n0, D_, false);
    __syncthreads();
    float c[4][2] = {};
    fkC<D_>(Asf, Wsf, c);
#pragma unroll
    for (int i = 0; i < 4; i++) {
        int row = m0 + ty * 4 + i, col = n0 + tx * 2;
        float2 rv = *(const float2*)&res[(size_t)row * D_ + col];
        float2 o;
        o.x = c[i][0] + bias[col + 0] + rv.x;
        o.y = c[i][1] + bias[col + 1] + rv.y;
        *(float2*)&C[(size_t)row * D_ + col] = o;
    }
}

// ---------------- rec_t ----------------
__global__ void __launch_bounds__(256) rec_t_kernel(
    float* __restrict__ ERR, const float* __restrict__ Kmat, const float* __restrict__ Vmat)
{
    __shared__ float sK[NT_][D_ + 1];
    __shared__ float Acf[NT_][NT_];
    __shared__ float cd[NT_];
    int b = blockIdx.x, tid = threadIdx.x;
    if (tid < NT_) cd[tid] = cdv(tid);
    for (int idx = tid; idx < NT_ * D_; idx += 256)
        sK[idx / D_][idx % D_] = Kmat[(size_t)b * NT_ * D_ + idx];
    __syncthreads();
    const int NP = NT_ * (NT_ - 1) / 2;
    for (int p = tid; p < NP; p += 256) {
        int i = (int)((1.0f + sqrtf(1.0f + 8.0f * (float)p)) * 0.5f);
        while (i * (i - 1) / 2 > p) i--;
        while ((i + 1) * i / 2 <= p) i++;
        int j = p - i * (i - 1) / 2;
        float s0 = 0.f, s1 = 0.f;
#pragma unroll 8
        for (int kk = 0; kk < D_; kk += 2) {
            s0 = fmaf(sK[j][kk],     sK[i][kk],     s0);
            s1 = fmaf(sK[j][kk + 1], sK[i][kk + 1], s1);
        }
        Acf[j][i] = cd[i - 1 - j] * (s0 + s1);
    }
    __syncthreads();
    if (tid < D_) {
        float err[NT_];
#pragma unroll
        for (int i = 0; i < NT_; i++) {
            float a0 = 0.f, a1 = 0.f;
#pragma unroll
            for (int j = 0; j < i; j++) {
                if (j & 1) a1 = fmaf(Acf[j][i], err[j], a1);
                else       a0 = fmaf(Acf[j][i], err[j], a0);
            }
            err[i] = Vmat[(size_t)(b * NT_ + i) * D_ + tid] - a0 - a1;
            ERR[(size_t)(b * NT_ + i) * D_ + tid] = err[i];
        }
    }
}

// ---------------- qkfinal ----------------
__global__ void __launch_bounds__(192) qkfinal(
    const float* __restrict__ x3, const float* __restrict__ Kt, const float* __restrict__ Et,
    const float* __restrict__ g2, const float* __restrict__ b2, float* __restrict__ pp)
{
    extern __shared__ __align__(16) float sh[];
    float (*sKT)[33] = (float (*)[33])sh;
    float* sEt = sh + 192 * 33;
    float* red = sEt + NT_ * D_;
    float* alpha = red + 192;
    float* cd = alpha + 32;
    float* lred = cd + 32;
    int blk = blockIdx.x;
    int b = blk >> 4, tc = blk & 15, t0 = tc * 16;
    int tid = threadIdx.x;
    if (tid < NT_) cd[tid] = cdv(tid);
    for (int idx = tid; idx < NT_ * D_; idx += 192) {
        int j = idx / D_, e = idx % D_;
        sKT[e][j] = Kt[(size_t)(b * NT_ + j) * D_ + e];
        sEt[idx] = Et[(size_t)b * NT_ * D_ + idx];
    }
    __syncthreads();
    int j = tid & 31, g = tid >> 5;
    float ps = 0.f;
    for (int tt = 0; tt < 16; tt++) {
        int t = t0 + tt, row = b * T_ + t, r = t >> 3;
        {
            const float* qr = x3 + (size_t)row * D_;
            float part = 0.f;
#pragma unroll
            for (int u = 0; u < 32; u++) part = fmaf(qr[g * 32 + u], sKT[g * 32 + u][j], part);
            red[j * 6 + g] = part;
        }
        __syncthreads();
        if (tid < NT_) {
            float s = 0.f;
#pragma unroll
            for (int gg = 0; gg < 6; gg++) s += red[tid * 6 + gg];
            alpha[tid] = (tid <= r) ? cd[r - tid] * s : 0.f;
        }
        __syncthreads();
        float s = 0.f;
        for (int jj = 0; jj <= r; jj++) s = fmaf(alpha[jj], sEt[jj * D_ + tid], s);
        float x4 = x3[(size_t)row * D_ + tid] + 0.5f * s;
        float sm = x4, s2 = x4 * x4;
#pragma unroll
        for (int o = 16; o > 0; o >>= 1) {
            sm += __shfl_xor_sync(~0u, sm, o);
            s2 += __shfl_xor_sync(~0u, s2, o);
        }
        if ((tid & 31) == 0) { lred[tid >> 5] = sm; lred[6 + (tid >> 5)] = s2; }
        __syncthreads();
        float ts = 0.f, ts2 = 0.f;
#pragma unroll
        for (int i = 0; i < 6; i++) { ts += lred[i]; ts2 += lred[6 + i]; }
        float m = ts / D_;
        float var = ts2 / D_ - m * m;
        ps += (x4 - m) * rsqrtf(var + EPS_) * g2[tid] + b2[tid];
        __syncthreads();
    }
    pp[(size_t)(b * 16 + tc) * D_ + tid] = ps;
}

// ---------------- pool + classifier ----------------
__global__ void __launch_bounds__(192) poolcls(
    const float* __restrict__ pp, const float* __restrict__ Wc,
    const float* __restrict__ bc, float* __restrict__ out)
{
    __shared__ float pooled[D_];
    int b = blockIdx.x, tid = threadIdx.x;
    float s = 0.f;
#pragma unroll
    for (int q = 0; q < 16; q++) s += pp[(size_t)(b * 16 + q) * D_ + tid];
    pooled[tid] = s * (1.f / T_);
    __syncthreads();
    if (tid < NC_) {
        float acc = bc[tid];
#pragma unroll 8
        for (int e = 0; e < D_; e++) acc = fmaf(pooled[e], Wc[e * NC_ + tid], acc);
        out[b * NC_ + tid] = acc;
    }
}

// =====================================================================
extern "C" void kernel_launch(void* const* d_in, const int* in_sizes, int n_in,
                              void* d_out, int out_size)
{
    const float* x     = (const float*)d_in[0];
    const float* W_in  = (const float*)d_in[1];
    const float* b_in  = (const float*)d_in[2];
    const float* Wv_a  = (const float*)d_in[3];
    const float* bv_a  = (const float*)d_in[4];
    const float* Wo_a  = (const float*)d_in[5];
    const float* bo_a  = (const float*)d_in[6];
    const float* ln1_g = (const float*)d_in[7];
    const float* ln1_b = (const float*)d_in[8];
    const float* pw1_w = (const float*)d_in[9];
    const float* pw1_b = (const float*)d_in[10];
    const float* dw_w  = (const float*)d_in[11];
    const float* dw_b  = (const float*)d_in[12];
    const float* bn_s  = (const float*)d_in[13];
    const float* bn_b  = (const float*)d_in[14];
    const float* pw2_w = (const float*)d_in[15];
    const float* pw2_b = (const float*)d_in[16];
    const float* Wk_t  = (const float*)d_in[17];
    const float* Wv_t  = (const float*)d_in[18];
    const float* Wq_t  = (const float*)d_in[19];
    const float* Wk_d  = (const float*)d_in[20];
    const float* Wv_d  = (const float*)d_in[21];
    const float* Wq_d  = (const float*)d_in[22];
    const float* ln2_g = (const float*)d_in[23];
    const float* ln2_b = (const float*)d_in[24];
    const float* Wc    = (const float*)d_in[25];
    const float* bc    = (const float*)d_in[26];
    float* out = (float*)d_out;

    float *xp, *x2, *g2p, *x3, *Kd, *Vd, *Qd, *Ed, *Fd, *Kt, *Vt, *Qt, *Et;
    float *Wao, *bao, *Wkqd, *Wkqt, *pp;
    cudaGetSymbolAddress((void**)&xp,   g_xp);
    cudaGetSymbolAddress((void**)&x2,   g_x2);
    cudaGetSymbolAddress((void**)&g2p,  g_g2);
    cudaGetSymbolAddress((void**)&x3,   g_x3);
    cudaGetSymbolAddress((void**)&Kd,   g_Kd);
    cudaGetSymbolAddress((void**)&Vd,   g_Vd);
    cudaGetSymbolAddress((void**)&Qd,   g_Qd);
    cudaGetSymbolAddress((void**)&Ed,   g_Ed);
    cudaGetSymbolAddress((void**)&Fd,   g_Fd);
    cudaGetSymbolAddress((void**)&Kt,   g_Kt);
    cudaGetSymbolAddress((void**)&Vt,   g_Vt);
    cudaGetSymbolAddress((void**)&Qt,   g_Qt);
    cudaGetSymbolAddress((void**)&Et,   g_Et);
    cudaGetSymbolAddress((void**)&Wao,  g_Wao);
    cudaGetSymbolAddress((void**)&bao,  g_bao);
    cudaGetSymbolAddress((void**)&Wkqd, g_Wkqd);
    cudaGetSymbolAddress((void**)&Wkqt, g_Wkqt);
    cudaGetSymbolAddress((void**)&pp,   g_pp);

    const int X2_SMEM  = GEMM_SMEM + (ND_ * D_ * 2 + 256) * 4;
    const int GLU_SMEM = (ASF_FLOATS + 2 * WSF_FLOATS + 256 + 256 + 64 + 64) * 4;
    const int QKF_SMEM = (192 * 33 + NT_ * D_ + 192 + 32 + 32 + 12) * 4;
    cudaFuncSetAttribute(k0_comb,  cudaFuncAttributeMaxDynamicSharedMemorySize, GEMM_SMEM);
    cudaFuncSetAttribute(x2_fused, cudaFuncAttributeMaxDynamicSharedMemorySize, X2_SMEM);
    cudaFuncSetAttribute(glu_ln,   cudaFuncAttributeMaxDynamicSharedMemorySize, GLU_SMEM);
    cudaFuncSetAttribute(gemm_pw2, cudaFuncAttributeMaxDynamicSharedMemorySize, GEMM_SMEM);
    cudaFuncSetAttribute(qkfinal,  cudaFuncAttributeMaxDynamicSharedMemorySize, QKF_SMEM);

    k0_comb<<<247, 256, GEMM_SMEM>>>(x, W_in, b_in, Wv_a, Wo_a, bv_a, bo_a,
                                     Wk_d, Wq_d, Wk_t, Wq_t);
    projKVQ<<<B_ * ND_, 192>>>(Kd, Vd, Qd, xp, Wk_d, Wv_d, Wkqd, ND_, 64);
    rec_d_kernel<<<B_, 256>>>(Ed, Fd, Kd, Vd, Wao);
    x2_fused<<<192, 256, X2_SMEM>>>(xp, Wao, bao, Qd, Fd, x2);
    glu_ln<<<192, 256, GLU_SMEM>>>(x2, ln1_g, ln1_b, pw1_w, pw1_b, dw_w, dw_b, bn_s, bn_b, g2p);
    gemm_pw2<<<192, 256, GEMM_SMEM>>>(g2p, pw2_w, pw2_b, x2, x3);
    projKVQ<<<B_ * NT_, 192>>>(Kt, Vt, Qt, x3, Wk_t, Wv_t, Wkqt, NT_, 8);
    rec_t_kernel<<<B_, 256>>>(Et, Kt, Vt);
    qkfinal<<<B_ * 16, 192, QKF_SMEM>>>(x3, Qt, Et, ln2_g, ln2_b, pp);
    poolcls<<<B_, 192>>>(pp, Wc, bc, out);
}

// round 11
// speedup vs baseline: 1.1404x; 1.1153x over previous
#include <cuda_runtime.h>
#include <math.h>

#define B_   8
#define T_   256
#define MEL_ 128
#define D_   192
#define NC_  20
#define D2_  384
#define NT_  32
#define ND_  4
#define EPS_ 1e-5f

__device__ float g_xp [B_*T_*D_];
__device__ float g_x1 [B_*T_*D_];
__device__ float g_x2 [B_*T_*D_];
__device__ float g_h  [B_*T_*D_];
__device__ float g_g2 [B_*T_*D_];
__device__ float g_x3 [B_*T_*D_];
__device__ float g_Kd [B_*ND_*D_];
__device__ float g_Vd [B_*ND_*D_];
__device__ float g_Qd [B_*ND_*D_];
__device__ float g_Ed [B_*ND_*D_];
__device__ float g_Kt [B_*NT_*D_];
__device__ float g_Vt [B_*NT_*D_];
__device__ float g_Qt [B_*NT_*D_];
__device__ float g_Et [B_*NT_*D_];
__device__ float g_Wao [D_*D_];
__device__ float g_bao [D_];
__device__ float g_Wkqd[D_*D_];
__device__ float g_Wkqt[D_*D_];
__device__ float g_pp [B_*16*D_];

// ---- PDL: let the next kernel in the stream launch early; wait for predecessor ----
__device__ __forceinline__ void gdc_launch() {
    asm volatile("griddepcontrol.launch_dependents;" ::: "memory");
}
__device__ __forceinline__ void gdc_wait() {
    asm volatile("griddepcontrol.wait;" ::: "memory");
}

__device__ __forceinline__ float cdv(int d) {
    const float L2A = -0.014499569695115089f;   // log2(0.99)
    const float L2E = -0.152003093445049970f;   // log2(0.90)
    float n = (float)(d + 1);
    return (exp2f(n * L2A) - exp2f(n * L2E)) * (0.1f / 0.09f);
}

// ---------------- R3-style tiled GEMM device fn: 64x64 tile, BK=16, 256 threads ----------------
__device__ __forceinline__ void dev_gemm_tile(float* sh,
    const float* __restrict__ A, int ldA, const float* __restrict__ W, int ldW, bool transB,
    const float* __restrict__ bias, const float* __restrict__ res, float* __restrict__ C, int ldC,
    int m0, int n0, int K)
{
    float (*As)[68] = (float (*)[68])sh;
    float (*Ws)[64] = (float (*)[64])(sh + 16 * 68);
    int tid = threadIdx.x;
    int tx = tid & 15, ty = tid >> 4;
    float c[4][4] = {};
    for (int k0 = 0; k0 < K; k0 += 16) {
        {
            int arow = tid >> 2, acol = (tid & 3) * 4;
            float4 v = *(const float4*)&A[(size_t)(m0 + arow) * ldA + k0 + acol];
            As[acol + 0][arow] = v.x; As[acol + 1][arow] = v.y;
            As[acol + 2][arow] = v.z; As[acol + 3][arow] = v.w;
        }
        {
            int wrow = tid >> 4, wcol = (tid & 15) * 4;
            if (transB) {
#pragma unroll
                for (int u = 0; u < 4; u++)
                    Ws[wrow][wcol + u] = W[(size_t)(n0 + wcol + u) * ldW + k0 + wrow];
            } else {
                *(float4*)&Ws[wrow][wcol] = *(const float4*)&W[(size_t)(k0 + wrow) * ldW + n0 + wcol];
            }
        }
        __syncthreads();
#pragma unroll
        for (int kk = 0; kk < 16; kk++) {
            float4 af = *(const float4*)&As[kk][ty * 4];
            float4 bf = *(const float4*)&Ws[kk][tx * 4];
            float a4[4] = {af.x, af.y, af.z, af.w};
            float b4[4] = {bf.x, bf.y, bf.z, bf.w};
#pragma unroll
            for (int i = 0; i < 4; i++)
#pragma unroll
                for (int j = 0; j < 4; j++) c[i][j] = fmaf(a4[i], b4[j], c[i][j]);
        }
        __syncthreads();
    }
#pragma unroll
    for (int i = 0; i < 4; i++) {
        int row = m0 + ty * 4 + i, col = n0 + tx * 4;
        float4 o; float* po = &o.x;
#pragma unroll
        for (int j = 0; j < 4; j++) {
            float v = c[i][j];
            if (bias) v += bias[col + j];
            if (res)  v += res[(size_t)row * ldC + col + j];
            po[j] = v;
        }
        *(float4*)&C[(size_t)row * ldC + col] = o;
    }
}

// ---------------- K0: xp GEMM (96) + Wao (9) + Wkqd (9) + Wkqt (9) + bao (1) ----------------
__global__ void __launch_bounds__(256) k0_comb(
    const float* __restrict__ x, const float* __restrict__ W_in, const float* __restrict__ b_in,
    const float* __restrict__ Wv_a, const float* __restrict__ Wo_a,
    const float* __restrict__ bv_a, const float* __restrict__ bo_a,
    const float* __restrict__ Wk_d, const float* __restrict__ Wq_d,
    const float* __restrict__ Wk_t, const float* __restrict__ Wq_t)
{
    __shared__ __align__(16) float sh[16 * 68 + 16 * 64];
    gdc_launch();
    gdc_wait();
    int blk = blockIdx.x, tid = threadIdx.x;
    if (blk < 96) {
        dev_gemm_tile(sh, x, MEL_, W_in, D_, false, b_in, nullptr, g_xp, D_,
                      (blk / 3) * 64, (blk % 3) * 64, MEL_);
    } else if (blk < 105) {
        int p = blk - 96;
        dev_gemm_tile(sh, Wv_a, D_, Wo_a, D_, false, nullptr, nullptr, g_Wao, D_,
                      (p / 3) * 64, (p % 3) * 64, D_);
    } else if (blk < 114) {
        int p = blk - 105;
        dev_gemm_tile(sh, Wk_d, D_, Wq_d, D_, true, nullptr, nullptr, g_Wkqd, D_,
                      (p / 3) * 64, (p % 3) * 64, D_);
    } else if (blk < 123) {
        int p = blk - 114;
        dev_gemm_tile(sh, Wk_t, D_, Wq_t, D_, true, nullptr, nullptr, g_Wkqt, D_,
                      (p / 3) * 64, (p % 3) * 64, D_);
    } else {
        if (tid < D_) {
            float s = bo_a[tid];
#pragma unroll 8
            for (int e = 0; e < D_; e++) s = fmaf(bv_a[e], Wo_a[e * D_ + tid], s);
            g_bao[tid] = s;
        }
    }
}

// ---------------- generic GEMM stage: C = A@W (+bias)(+res), M=2048, N=K=192, grid 96 ----------------
__global__ void __launch_bounds__(256) gemm_generic(
    float* __restrict__ C, const float* __restrict__ A, const float* __restrict__ W,
    const float* __restrict__ bias, const float* __restrict__ res)
{
    __shared__ __align__(16) float sh[16 * 68 + 16 * 64];
    gdc_launch();
    gdc_wait();
    dev_gemm_tile(sh, A, D_, W, D_, false, bias, res, C, D_,
                  (blockIdx.x / 3) * 64, (blockIdx.x % 3) * 64, D_);
}

// ---------------- projKVQ: K/V/Ktilde for gathered rows ----------------
__global__ void __launch_bounds__(192) projKVQ(
    float* __restrict__ Ko, float* __restrict__ Vo, float* __restrict__ Qo,
    const float* __restrict__ A, const float* __restrict__ Wk,
    const float* __restrict__ Wv, const float* __restrict__ Wkq, int nUpd, int chunk)
{
    __shared__ float sa[D_];
    gdc_launch();
    gdc_wait();
    int blk = blockIdx.x;
    int b = blk / nUpd, i = blk % nUpd;
    int tid = threadIdx.x;
    sa[tid] = A[(size_t)(b * T_ + i * chunk) * D_ + tid];
    __syncthreads();
    if (tid < 144) {
        int gsel = tid / 48, q = tid % 48;
        const float* W = (gsel == 0) ? Wk : (gsel == 1) ? Wv : Wkq;
        float ax = 0.f, ay = 0.f, az = 0.f, aw = 0.f;
#pragma unroll 16
        for (int kk = 0; kk < D_; kk++) {
            float a = sa[kk];
            float4 w = *(const float4*)&W[kk * D_ + 4 * q];
            ax = fmaf(a, w.x, ax); ay = fmaf(a, w.y, ay);
            az = fmaf(a, w.z, az); aw = fmaf(a, w.w, aw);
        }
        float* O = (gsel == 0) ? Ko : (gsel == 1) ? Vo : Qo;
        float4 o = {ax, ay, az, aw};
        *(float4*)&O[(size_t)blk * D_ + 4 * q] = o;
    }
}

// ---------------- rec_d: delta err recurrence ----------------
__global__ void __launch_bounds__(256) rec_d_kernel(
    float* __restrict__ ERR, const float* __restrict__ Kmat, const float* __restrict__ Vmat)
{
    __shared__ float sK[ND_][D_ + 1];
    __shared__ float Acf[ND_][ND_];
    gdc_launch();
    gdc_wait();
    int b = blockIdx.x, tid = threadIdx.x;
    for (int idx = tid; idx < ND_ * D_; idx += 256)
        sK[idx / D_][idx % D_] = Kmat[(size_t)b * ND_ * D_ + idx];
    __syncthreads();
    if (tid < 6) {
        const int pi[6] = {1, 2, 2, 3, 3, 3};
        const int pj[6] = {0, 0, 1, 0, 1, 2};
        int i = pi[tid], j = pj[tid];
        float s0 = 0.f, s1 = 0.f;
#pragma unroll 8
        for (int kk = 0; kk < D_; kk += 2) {
            s0 = fmaf(sK[j][kk],     sK[i][kk],     s0);
            s1 = fmaf(sK[j][kk + 1], sK[i][kk + 1], s1);
        }
        Acf[j][i] = cdv(i - 1 - j) * (s0 + s1);
    }
    __syncthreads();
    if (tid < D_) {
        float err[ND_];
#pragma unroll
        for (int i = 0; i < ND_; i++) {
            float s = Vmat[(size_t)(b * ND_ + i) * D_ + tid];
#pragma unroll
            for (int j = 0; j < i; j++) s -= Acf[j][i] * err[j];
            err[i] = s;
            ERR[(size_t)(b * ND_ + i) * D_ + tid] = s;
        }
    }
}

// ---------------- qkx1: x1 = xp + 0.5 * delta retrieval (QK via folded keys) ----------------
__global__ void __launch_bounds__(192) qkx1_kernel(
    float* __restrict__ x1, const float* __restrict__ xp,
    const float* __restrict__ Ktil, const float* __restrict__ Ed)
{
    __shared__ float sK[ND_][D_];
    __shared__ float sE[ND_][D_];
    __shared__ float red[ND_][6];
    __shared__ float alpha[ND_];
    gdc_launch();
    gdc_wait();
    int bt = blockIdx.x;
    int b = bt / T_, t = bt % T_, r = t >> 6;
    int e = threadIdx.x;
#pragma unroll
    for (int j = 0; j < ND_; j++) {
        sK[j][e] = Ktil[(size_t)(b * ND_ + j) * D_ + e];
        sE[j][e] = Ed[(size_t)(b * ND_ + j) * D_ + e];
    }
    __syncthreads();
    float q = xp[(size_t)bt * D_ + e];
    float p[ND_];
#pragma unroll
    for (int j = 0; j < ND_; j++) p[j] = q * sK[j][e];
#pragma unroll
    for (int o = 16; o > 0; o >>= 1)
#pragma unroll
        for (int j = 0; j < ND_; j++) p[j] += __shfl_xor_sync(~0u, p[j], o);
    int w = e >> 5, l = e & 31;
    if (l == 0)
#pragma unroll
        for (int j = 0; j < ND_; j++) red[j][w] = p[j];
    __syncthreads();
    if (e < ND_) {
        float s = 0.f;
#pragma unroll
        for (int w2 = 0; w2 < 6; w2++) s += red[e][w2];
        alpha[e] = (e <= r) ? cdv(r - e) * s : 0.f;
    }
    __syncthreads();
    float s = 0.f;
#pragma unroll
    for (int j = 0; j < ND_; j++) s = fmaf(alpha[j], sE[j][e], s);
    x1[(size_t)bt * D_ + e] = q + 0.5f * s;
}

// ---------------- LayerNorm ----------------
__global__ void __launch_bounds__(192) ln_kernel(
    float* __restrict__ outp, const float* __restrict__ in,
    const float* __restrict__ g, const float* __restrict__ bta)
{
    __shared__ float red[2][6];
    gdc_launch();
    gdc_wait();
    int row = blockIdx.x, e = threadIdx.x;
    float v = in[(size_t)row * D_ + e];
    float s = v, s2 = v * v;
#pragma unroll
    for (int o = 16; o > 0; o >>= 1) {
        s  += __shfl_xor_sync(~0u, s,  o);
        s2 += __shfl_xor_sync(~0u, s2, o);
    }
    int w = e >> 5, l = e & 31;
    if (l == 0) { red[0][w] = s; red[1][w] = s2; }
    __syncthreads();
    float ts = 0.f, ts2 = 0.f;
#pragma unroll
    for (int i = 0; i < 6; i++) { ts += red[0][i]; ts2 += red[1][i]; }
    float m = ts / D_;
    float var = ts2 / D_ - m * m;
    outp[(size_t)row * D_ + e] = (v - m) * rsqrtf(var + EPS_) * g[e] + bta[e];
}

// ---------------- gemm_glu: R3-style N=384 GEMM with GLU+dw+BN+SiLU epilogue ----------------
__global__ void __launch_bounds__(256) gemm_glu(
    float* __restrict__ outp, const float* __restrict__ A, const float* __restrict__ W,
    const float* __restrict__ bias,
    const float* __restrict__ dw, const float* __restrict__ db,
    const float* __restrict__ bs, const float* __restrict__ bb)
{
    __shared__ __align__(16) float As[16][68];
    __shared__ __align__(16) float Wsa[16][64];
    __shared__ __align__(16) float Wsg[16][64];
    gdc_launch();
    gdc_wait();
    int blk = blockIdx.x;
    int m0 = (blk / 3) * 64, n0 = (blk % 3) * 64;
    int tid = threadIdx.x;
    int tx = tid & 15, ty = tid >> 4;
    float cA[4][4] = {}, cG[4][4] = {};
    for (int k0 = 0; k0 < D_; k0 += 16) {
        {
            int arow = tid >> 2, acol = (tid & 3) * 4;
            float4 v = *(const float4*)&A[(size_t)(m0 + arow) * D_ + k0 + acol];
            As[acol + 0][arow] = v.x; As[acol + 1][arow] = v.y;
            As[acol + 2][arow] = v.z; As[acol + 3][arow] = v.w;
        }
        {
            int wrow = tid >> 4, wcol = (tid & 15) * 4;
            float4 va = *(const float4*)&W[(size_t)(k0 + wrow) * D2_ + n0 + wcol];
            float4 vg = *(const float4*)&W[(size_t)(k0 + wrow) * D2_ + D_ + n0 + wcol];
            *(float4*)&Wsa[wrow][wcol] = va;
            *(float4*)&Wsg[wrow][wcol] = vg;
        }
        __syncthreads();
#pragma unroll
        for (int kk = 0; kk < 16; kk++) {
            float4 af = *(const float4*)&As[kk][ty * 4];
            float4 ba = *(const float4*)&Wsa[kk][tx * 4];
            float4 bg = *(const float4*)&Wsg[kk][tx * 4];
            float a4[4] = {af.x, af.y, af.z, af.w};
            float p4[4] = {ba.x, ba.y, ba.z, ba.w};
            float q4[4] = {bg.x, bg.y, bg.z, bg.w};
#pragma unroll
            for (int i = 0; i < 4; i++)
#pragma unroll
                for (int j = 0; j < 4; j++) {
                    cA[i][j] = fmaf(a4[i], p4[j], cA[i][j]);
                    cG[i][j] = fmaf(a4[i], q4[j], cG[i][j]);
                }
        }
        __syncthreads();
    }
#pragma unroll
    for (int i = 0; i < 4; i++) {
        int row = m0 + ty * 4 + i, col = n0 + tx * 4;
        float4 o; float* po = &o.x;
#pragma unroll
        for (int j = 0; j < 4; j++) {
            float a = cA[i][j] + bias[col + j];
            float g = cG[i][j] + bias[D_ + col + j];
            float h = a * (1.f / (1.f + expf(-g)));
            h = h * dw[col + j] + db[col + j];
            h = h * bs[col + j] + bb[col + j];
            h = h * (1.f / (1.f + expf(-h)));
            po[j] = h;
        }
        *(float4*)&outp[(size_t)row * D_ + col] = o;
    }
}

// ---------------- rec_t: theta err recurrence ----------------
__global__ void __launch_bounds__(256) rec_t_kernel(
    float* __restrict__ ERR, const float* __restrict__ Kmat, const float* __restrict__ Vmat)
{
    __shared__ float sK[NT_][D_ + 1];
    __shared__ float Acf[NT_][NT_];
    __shared__ float cd[NT_];
    gdc_launch();
    gdc_wait();
    int b = blockIdx.x, tid = threadIdx.x;
    if (tid < NT_) cd[tid] = cdv(tid);
    for (int idx = tid; idx < NT_ * D_; idx += 256)
        sK[idx / D_][idx % D_] = Kmat[(size_t)b * NT_ * D_ + idx];
    __syncthreads();
    const int NP = NT_ * (NT_ - 1) / 2;
    for (int p = tid; p < NP; p += 256) {
        int i = (int)((1.0f + sqrtf(1.0f + 8.0f * (float)p)) * 0.5f);
        while (i * (i - 1) / 2 > p) i--;
        while ((i + 1) * i / 2 <= p) i++;
        int j = p - i * (i - 1) / 2;
        float s0 = 0.f, s1 = 0.f;
#pragma unroll 8
        for (int kk = 0; kk < D_; kk += 2) {
            s0 = fmaf(sK[j][kk],     sK[i][kk],     s0);
            s1 = fmaf(sK[j][kk + 1], sK[i][kk + 1], s1);
        }
        Acf[j][i] = cd[i - 1 - j] * (s0 + s1);
    }
    __syncthreads();
    if (tid < D_) {
        float err[NT_];
#pragma unroll
        for (int i = 0; i < NT_; i++) {
            float a0 = 0.f, a1 = 0.f;
#pragma unroll
            for (int j = 0; j < i; j++) {
                if (j & 1) a1 = fmaf(Acf[j][i], err[j], a1);
                else       a0 = fmaf(Acf[j][i], err[j], a0);
            }
            err[i] = Vmat[(size_t)(b * NT_ + i) * D_ + tid] - a0 - a1;
            ERR[(size_t)(b * NT_ + i) * D_ + tid] = err[i];
        }
    }
}

// ---------------- qkfinal: theta retrieval + x4 + LN2 -> partial pools ----------------
__global__ void __launch_bounds__(192) qkfinal(
    const float* __restrict__ x3, const float* __restrict__ Kt, const float* __restrict__ Et,
    const float* __restrict__ g2, const float* __restrict__ b2, float* __restrict__ pp)
{
    extern __shared__ __align__(16) float sh[];
    float (*sKT)[33] = (float (*)[33])sh;
    float* sEt = sh + 192 * 33;
    float* red = sEt + NT_ * D_;
    float* alpha = red + 192;
    float* cd = alpha + 32;
    float* lred = cd + 32;
    gdc_launch();
    gdc_wait();
    int blk = blockIdx.x;
    int b = blk >> 4, tc = blk & 15, t0 = tc * 16;
    int tid = threadIdx.x;
    if (tid < NT_) cd[tid] = cdv(tid);
    for (int idx = tid; idx < NT_ * D_; idx += 192) {
        int j = idx / D_, e = idx % D_;
        sKT[e][j] = Kt[(size_t)(b * NT_ + j) * D_ + e];
        sEt[idx] = Et[(size_t)b * NT_ * D_ + idx];
    }
    __syncthreads();
    int j = tid & 31, g = tid >> 5;
    float ps = 0.f;
    for (int tt = 0; tt < 16; tt++) {
        int t = t0 + tt, row = b * T_ + t, r = t >> 3;
        {
            const float* qr = x3 + (size_t)row * D_;
            float part = 0.f;
#pragma unroll
            for (int u = 0; u < 32; u++) part = fmaf(qr[g * 32 + u], sKT[g * 32 + u][j], part);
            red[j * 6 + g] = part;
        }
        __syncthreads();
        if (tid < NT_) {
            float s = 0.f;
#pragma unroll
            for (int gg = 0; gg < 6; gg++) s += red[tid * 6 + gg];
            alpha[tid] = (tid <= r) ? cd[r - tid] * s : 0.f;
        }
        __syncthreads();
        float s = 0.f;
        for (int jj = 0; jj <= r; jj++) s = fmaf(alpha[jj], sEt[jj * D_ + tid], s);
        float x4 = x3[(size_t)row * D_ + tid] + 0.5f * s;
        float sm = x4, s2 = x4 * x4;
#pragma unroll
        for (int o = 16; o > 0; o >>= 1) {
            sm += __shfl_xor_sync(~0u, sm, o);
            s2 += __shfl_xor_sync(~0u, s2, o);
        }
        if ((tid & 31) == 0) { lred[tid >> 5] = sm; lred[6 + (tid >> 5)] = s2; }
        __syncthreads();
        float ts = 0.f, ts2 = 0.f;
#pragma unroll
        for (int i = 0; i < 6; i++) { ts += lred[i]; ts2 += lred[6 + i]; }
        float m = ts / D_;
        float var = ts2 / D_ - m * m;
        ps += (x4 - m) * rsqrtf(var + EPS_) * g2[tid] + b2[tid];
        __syncthreads();
    }
    pp[(size_t)(b * 16 + tc) * D_ + tid] = ps;
}

// ---------------- pool + classifier ----------------
__global__ void __launch_bounds__(192) poolcls(
    const float* __restrict__ pp, const float* __restrict__ Wc,
    const float* __restrict__ bc, float* __restrict__ out)
{
    __shared__ float pooled[D_];
    gdc_launch();
    gdc_wait();
    int b = blockIdx.x, tid = threadIdx.x;
    float s = 0.f;
#pragma unroll
    for (int q = 0; q < 16; q++) s += pp[(size_t)(b * 16 + q) * D_ + tid];
    pooled[tid] = s * (1.f / T_);
    __syncthreads();
    if (tid < NC_) {
        float acc = bc[tid];
#pragma unroll 8
        for (int e = 0; e < D_; e++) acc = fmaf(pooled[e], Wc[e * NC_ + tid], acc);
        out[b * NC_ + tid] = acc;
    }
}

// ---------------- PDL launch helper ----------------
static void launch_pdl(const void* fn, dim3 grid, dim3 block, size_t smem, void** args)
{
    cudaLaunchConfig_t cfg = {};
    cfg.gridDim = grid;
    cfg.blockDim = block;
    cfg.dynamicSmemBytes = smem;
    cfg.stream = 0;
    cudaLaunchAttribute at[1];
    at[0].id = cudaLaunchAttributeProgrammaticStreamSerialization;
    at[0].val.programmaticStreamSerializationAllowed = 1;
    cfg.attrs = at;
    cfg.numAttrs = 1;
    cudaLaunchKernelExC(&cfg, fn, args);
}

// =====================================================================
extern "C" void kernel_launch(void* const* d_in, const int* in_sizes, int n_in,
                              void* d_out, int out_size)
{
    const float* x     = (const float*)d_in[0];
    const float* W_in  = (const float*)d_in[1];
    const float* b_in  = (const float*)d_in[2];
    const float* Wv_a  = (const float*)d_in[3];
    const float* bv_a  = (const float*)d_in[4];
    const float* Wo_a  = (const float*)d_in[5];
    const float* bo_a  = (const float*)d_in[6];
    const float* ln1_g = (const float*)d_in[7];
    const float* ln1_b = (const float*)d_in[8];
    const float* pw1_w = (const float*)d_in[9];
    const float* pw1_b = (const float*)d_in[10];
    const float* dw_w  = (const float*)d_in[11];
    const float* dw_b  = (const float*)d_in[12];
    const float* bn_s  = (const float*)d_in[13];
    const float* bn_b  = (const float*)d_in[14];
    const float* pw2_w = (const float*)d_in[15];
    const float* pw2_b = (const float*)d_in[16];
    const float* Wk_t  = (const float*)d_in[17];
    const float* Wv_t  = (const float*)d_in[18];
    const float* Wq_t  = (const float*)d_in[19];
    const float* Wk_d  = (const float*)d_in[20];
    const float* Wv_d  = (const float*)d_in[21];
    const float* Wq_d  = (const float*)d_in[22];
    const float* ln2_g = (const float*)d_in[23];
    const float* ln2_b = (const float*)d_in[24];
    const float* Wc    = (const float*)d_in[25];
    const float* bc    = (const float*)d_in[26];
    float* out = (float*)d_out;

    float *xp, *x1, *x2, *h, *g2p, *x3;
    float *Kd, *Vd, *Qd, *Ed, *Kt, *Vt, *Qt, *Et, *Wao, *bao, *Wkqd, *Wkqt, *pp;
    cudaGetSymbolAddress((void**)&xp,   g_xp);
    cudaGetSymbolAddress((void**)&x1,   g_x1);
    cudaGetSymbolAddress((void**)&x2,   g_x2);
    cudaGetSymbolAddress((void**)&h,    g_h);
    cudaGetSymbolAddress((void**)&g2p,  g_g2);
    cudaGetSymbolAddress((void**)&x3,   g_x3);
    cudaGetSymbolAddress((void**)&Kd,   g_Kd);
    cudaGetSymbolAddress((void**)&Vd,   g_Vd);
    cudaGetSymbolAddress((void**)&Qd,   g_Qd);
    cudaGetSymbolAddress((void**)&Ed,   g_Ed);
    cudaGetSymbolAddress((void**)&Kt,   g_Kt);
    cudaGetSymbolAddress((void**)&Vt,   g_Vt);
    cudaGetSymbolAddress((void**)&Qt,   g_Qt);
    cudaGetSymbolAddress((void**)&Et,   g_Et);
    cudaGetSymbolAddress((void**)&Wao,  g_Wao);
    cudaGetSymbolAddress((void**)&bao,  g_bao);
    cudaGetSymbolAddress((void**)&Wkqd, g_Wkqd);
    cudaGetSymbolAddress((void**)&Wkqt, g_Wkqt);
    cudaGetSymbolAddress((void**)&pp,   g_pp);

    const int QKF_SMEM = (192 * 33 + NT_ * D_ + 192 + 32 + 32 + 12) * 4;
    cudaFuncSetAttribute((const void*)qkfinal,
                         cudaFuncAttributeMaxDynamicSharedMemorySize, QKF_SMEM);

    int nUpd_d = ND_, chunk_d = 64, nUpd_t = NT_, chunk_t = 8;

    // 1) k0: xp GEMM + weight folds
    {
        void* a[] = {(void*)&x, (void*)&W_in, (void*)&b_in, (void*)&Wv_a, (void*)&Wo_a,
                     (void*)&bv_a, (void*)&bo_a, (void*)&Wk_d, (void*)&Wq_d,
                     (void*)&Wk_t, (void*)&Wq_t};
        launch_pdl((const void*)k0_comb, dim3(124), dim3(256), 0, a);
    }
    // 2) delta K/V/Ktilde
    {
        void* a[] = {(void*)&Kd, (void*)&Vd, (void*)&Qd, (void*)&xp,
                     (void*)&Wk_d, (void*)&Wv_d, (void*)&Wkqd, (void*)&nUpd_d, (void*)&chunk_d};
        launch_pdl((const void*)projKVQ, dim3(B_ * ND_), dim3(192), 0, a);
    }
    // 3) delta err recurrence
    {
        void* a[] = {(void*)&Ed, (void*)&Kd, (void*)&Vd};
        launch_pdl((const void*)rec_d_kernel, dim3(B_), dim3(256), 0, a);
    }
    // 4) x1 = xp + 0.5 * retrieval
    {
        void* a[] = {(void*)&x1, (void*)&xp, (void*)&Qd, (void*)&Ed};
        launch_pdl((const void*)qkx1_kernel, dim3(B_ * T_), dim3(192), 0, a);
    }
    // 5) x2 = x1 + x1@Wao + bao
    {
        void* a[] = {(void*)&x2, (void*)&x1, (void*)&Wao, (void*)&bao, (void*)&x1};
        launch_pdl((const void*)gemm_generic, dim3(96), dim3(256), 0, a);
    }
    // 6) h = LN1(x2)
    {
        void* a[] = {(void*)&h, (void*)&x2, (void*)&ln1_g, (void*)&ln1_b};
        launch_pdl((const void*)ln_kernel, dim3(B_ * T_), dim3(192), 0, a);
    }
    // 7) g2 = SiLU(BN(dw(GLU(h@pw1+b))))
    {
        void* a[] = {(void*)&g2p, (void*)&h, (void*)&pw1_w, (void*)&pw1_b,
                     (void*)&dw_w, (void*)&dw_b, (void*)&bn_s, (void*)&bn_b};
        launch_pdl((const void*)gemm_glu, dim3(96), dim3(256), 0, a);
    }
    // 8) x3 = x2 + g2@pw2 + b
    {
        void* a[] = {(void*)&x3, (void*)&g2p, (void*)&pw2_w, (void*)&pw2_b, (void*)&x2};
        launch_pdl((const void*)gemm_generic, dim3(96), dim3(256), 0, a);
    }
    // 9) theta K/V/Ktilde
    {
        void* a[] = {(void*)&Kt, (void*)&Vt, (void*)&Qt, (void*)&x3,
                     (void*)&Wk_t, (void*)&Wv_t, (void*)&Wkqt, (void*)&nUpd_t, (void*)&chunk_t};
        launch_pdl((const void*)projKVQ, dim3(B_ * NT_), dim3(192), 0, a);
    }
    // 10) theta err recurrence
    {
        void* a[] = {(void*)&Et, (void*)&Kt, (void*)&Vt};
        launch_pdl((const void*)rec_t_kernel, dim3(B_), dim3(256), 0, a);
    }
    // 11) retrieval + LN2 -> partial pools
    {
        void* a[] = {(void*)&x3, (void*)&Qt, (void*)&Et, (void*)&ln2_g, (void*)&ln2_b, (void*)&pp};
        launch_pdl((const void*)qkfinal, dim3(B_ * 16), dim3(192), QKF_SMEM, a);
    }
    // 12) pool + classifier
    {
        void* a[] = {(void*)&pp, (void*)&Wc, (void*)&bc, (void*)&out};
        launch_pdl((const void*)poolcls, dim3(B_), dim3(192), 0, a);
    }
}